// round 2
// baseline (speedup 1.0000x reference)
#include <cuda_runtime.h>
#include <cstdint>

// KVCacheManager update_cache, token-gen path.
//   L=2, B=4, H=8, M=4096, D=128, fp32
//   out shape: (2[kv], L, B, H, M, D)
//   out[kv,l,b,h,m,d] = (m == pos[b] && pos[b] < seq_len) ? latest[l,b,h,d]
//                                                         : cache[l,b,h,m,d]
//
// Pure HBM-bound streaming copy with fused point-scatter.
// float4-vectorized; linear float4 index bit layout (24 bits = 16,777,216):
//   d4 : bits [0:5)   (32 float4 per D=128 row)
//   m  : bits [5:17)  (4096)
//   h  : bits [17:20) (8)
//   b  : bits [20:22) (4)
//   l  : bit  [22]    (2)
//   kv : bit  [23]    (2)
// Within a warp all lanes share m,b -> the scatter branch is warp-uniform.

static constexpr unsigned TOTAL_VEC4 = 1u << 24;       // 16,777,216 float4s
static constexpr unsigned HALF_MASK  = (1u << 23) - 1; // index within one cache
static constexpr unsigned THREADS    = 256;
static constexpr unsigned VEC_PER_THREAD = 2;          // independent loads (MLP)
static constexpr unsigned GRID = TOTAL_VEC4 / (THREADS * VEC_PER_THREAD); // 32768

__device__ __forceinline__ float4 load_elem(
    unsigned i,
    const float4* __restrict__ k_cache,
    const float4* __restrict__ v_cache,
    const float4* __restrict__ latest_k,
    const float4* __restrict__ latest_v,
    const int* __restrict__ pos, int S)
{
    unsigned d4 = i & 31u;
    unsigned m  = (i >> 5)  & 4095u;
    unsigned h  = (i >> 17) & 7u;
    unsigned b  = (i >> 20) & 3u;
    unsigned l  = (i >> 22) & 1u;
    unsigned kv = (i >> 23) & 1u;
    unsigned ci = i & HALF_MASK;

    int p = __ldg(&pos[b]);
    if ((int)m == p && p < S) {
        // latest_{k,v}: (L,B,H,1,D) -> float4 index ((l*B+b)*H+h)*32 + d4
        unsigned li = ((((l << 2) + b) << 3) + h) * 32u + d4;
        return kv ? __ldg(&latest_v[li]) : __ldg(&latest_k[li]);
    }
    return kv ? __ldg(&v_cache[ci]) : __ldg(&k_cache[ci]);
}

__global__ void __launch_bounds__(THREADS)
kv_update_kernel(const float4* __restrict__ k_cache,
                 const float4* __restrict__ v_cache,
                 const float4* __restrict__ latest_k,
                 const float4* __restrict__ latest_v,
                 const int*    __restrict__ pos,
                 const int*    __restrict__ seq_len_p,
                 float4*       __restrict__ out)
{
    const unsigned span = GRID * THREADS;   // 8,388,608
    unsigned i0 = blockIdx.x * THREADS + threadIdx.x;
    unsigned i1 = i0 + span;

    int S = seq_len_p ? __ldg(seq_len_p) : 4096;

    // Two independent load chains -> MLP=2 per thread, both fully coalesced.
    float4 v0 = load_elem(i0, k_cache, v_cache, latest_k, latest_v, pos, S);
    float4 v1 = load_elem(i1, k_cache, v_cache, latest_k, latest_v, pos, S);
    out[i0] = v0;
    out[i1] = v1;
}

extern "C" void kernel_launch(void* const* d_in, const int* in_sizes, int n_in,
                              void* d_out, int out_size)
{
    // metadata order: k_caches, v_caches, latest_k, latest_v, position_ids, seq_len
    const float4* k_cache  = (const float4*)d_in[0];
    const float4* v_cache  = (const float4*)d_in[1];
    const float4* latest_k = (const float4*)d_in[2];
    const float4* latest_v = (const float4*)d_in[3];
    const int*    pos      = (const int*)d_in[4];
    const int*    seq_len  = (n_in >= 6) ? (const int*)d_in[5] : nullptr;
    float4*       out      = (float4*)d_out;

    kv_update_kernel<<<GRID, THREADS>>>(k_cache, v_cache, latest_k, latest_v,
                                        pos, seq_len, out);
    (void)in_sizes; (void)out_size;
}